// round 3
// baseline (speedup 1.0000x reference)
#include <cuda_runtime.h>
#include <cstdint>

// Problem constants (fixed shapes per reference)
#define B_DIM 8
#define P_DIM 65536
#define C_DIM 32768
#define F_DIM 32
#define E_DIM 524288
#define THREADS 256
#define WARPS 8

// Per-channel edge-range offsets (edge_channel is sorted)
__device__ int g_offs[C_DIM + 1];

// ---------- packed f32x2 helpers ----------
__device__ __forceinline__ unsigned long long ffma2(unsigned long long a,
                                                    unsigned long long b,
                                                    unsigned long long c) {
    unsigned long long d;
    asm("fma.rn.f32x2 %0, %1, %2, %3;" : "=l"(d) : "l"(a), "l"(b), "l"(c));
    return d;
}
__device__ __forceinline__ float hadd2(unsigned long long v) {
    float lo, hi;
    asm("mov.b64 {%0, %1}, %2;" : "=f"(lo), "=f"(hi) : "l"(v));
    return lo + hi;
}
__device__ __forceinline__ float fast_rcp(float x) {
    float r;
    asm("rcp.approx.f32 %0, %1;" : "=f"(r) : "f"(x));
    return r;
}
__device__ __forceinline__ float sigmoidf_fast(float x) {
    // 1 / (1 + e^-x): MUFU.EX2 + MUFU.RCP, rel err ~1e-7 — fine for 1e-3 tol
    return fast_rcp(1.0f + __expf(-x));
}
__device__ __forceinline__ float tanhf_fast(float x) {
    // tanh(x) = 2*sigmoid(2x) - 1 (saturates correctly at +/-1)
    return fmaf(2.0f, sigmoidf_fast(2.0f * x), -1.0f);
}

// ---------- kernel 1: segment offsets via binary search ----------
__global__ void offsets_kernel(const int* __restrict__ ec) {
    int c = blockIdx.x * blockDim.x + threadIdx.x;
    if (c > C_DIM) return;
    int lo = 0, hi = E_DIM;
    while (lo < hi) {
        int mid = (lo + hi) >> 1;
        if (ec[mid] < c) lo = mid + 1; else hi = mid;
    }
    g_offs[c] = lo;  // lower_bound(edge_channel, c); c == C_DIM -> E_DIM
}

// ---------- kernel 2: fused gather + GRU ----------
// One warp per channel; lane = feature index (F = 32 = warpSize).
__global__ __launch_bounds__(THREADS, 2)
void gru_kernel(const float* __restrict__ pf,   // path_features   [B,P,F]
                const float* __restrict__ hf,   // channel_features[B,C,F]
                const float* __restrict__ Wih,  // [3F,F]
                const float* __restrict__ Whh,  // [3F,F]
                const float* __restrict__ bih,  // [3F]
                const float* __restrict__ bhh,  // [3F]
                const int*   __restrict__ ep,   // edge_path [E]
                float*       __restrict__ out)  // [B,C,F]
{
    // W stored transposed and f-paired: sW[fp][row] = (W[row][2fp], W[row][2fp+1])
    __shared__ float2 sWih[16 * 96];
    __shared__ float2 sWhh[16 * 96];
    __shared__ float  sBias[128];
    // Per-warp staging: [0..255] = agg[b][f], [256..511] = h[b][f]
    __shared__ __align__(16) float sBuf[WARPS][512];

    const int tid = threadIdx.x;

    for (int i = tid; i < 16 * 96; i += THREADS) {
        int fp = i / 96, row = i % 96;
        sWih[i] = make_float2(Wih[row * 32 + 2 * fp], Wih[row * 32 + 2 * fp + 1]);
        sWhh[i] = make_float2(Whh[row * 32 + 2 * fp], Whh[row * 32 + 2 * fp + 1]);
    }
    if (tid < 32) {
        sBias[tid]      = bih[tid]      + bhh[tid];       // r bias (combined)
        sBias[32 + tid] = bih[32 + tid] + bhh[32 + tid];  // z bias (combined)
        sBias[64 + tid] = bih[64 + tid];                  // n input bias
        sBias[96 + tid] = bhh[64 + tid];                  // n hidden bias (inside r*)
    }
    __syncthreads();

    const int w = tid >> 5, lane = tid & 31;
    const int c = blockIdx.x * WARPS + w;

    // ---- gather: agg[b][lane] = sum over this channel's edges ----
    float agg[B_DIM];
#pragma unroll
    for (int b = 0; b < B_DIM; b++) agg[b] = 0.0f;

    const int s0 = g_offs[c], e0 = g_offs[c + 1];
    for (int base = s0; base < e0; base += 32) {
        int idx = base + lane;
        int pe  = (idx < e0) ? ep[idx] : 0;
        int m   = min(32, e0 - base);
        for (int i = 0; i < m; i++) {
            int p = __shfl_sync(0xffffffffu, pe, i);
            const float* src = pf + ((size_t)p << 5) + lane;  // coalesced 128B row
#pragma unroll
            for (int b = 0; b < B_DIM; b++) {
                agg[b] += __ldg(src);
                src += (size_t)P_DIM * F_DIM;
            }
        }
    }

    float* aggS = sBuf[w];
    float* hS   = sBuf[w] + 256;
    {
        const float* hsrc = hf + ((size_t)c << 5) + lane;
#pragma unroll
        for (int b = 0; b < B_DIM; b++) {
            aggS[b * 32 + lane] = agg[b];       // conflict-free STS
            hS[b * 32 + lane]   = __ldcs(hsrc); // streaming hint: keep pf in L2
            hsrc += (size_t)C_DIM * F_DIM;
        }
    }
    __syncwarp();

    // ---- GEMM: lane j computes gates r/z/n for output feature j, all b ----
    const unsigned long long* WI = (const unsigned long long*)sWih;
    const unsigned long long* WH = (const unsigned long long*)sWhh;
    const unsigned long long* AG = (const unsigned long long*)aggS;
    const unsigned long long* HS = (const unsigned long long*)hS;

    unsigned long long accr[B_DIM], accz[B_DIM], accxn[B_DIM], acchn[B_DIM];
#pragma unroll
    for (int b = 0; b < B_DIM; b++) { accr[b] = 0ull; accz[b] = 0ull; accxn[b] = 0ull; acchn[b] = 0ull; }

#pragma unroll 4
    for (int fp = 0; fp < 16; fp++) {
        unsigned long long wir = WI[fp * 96 + lane];       // conflict-free LDS.64
        unsigned long long wiz = WI[fp * 96 + 32 + lane];
        unsigned long long win = WI[fp * 96 + 64 + lane];
        unsigned long long whr = WH[fp * 96 + lane];
        unsigned long long whz = WH[fp * 96 + 32 + lane];
        unsigned long long whn = WH[fp * 96 + 64 + lane];
#pragma unroll
        for (int b = 0; b < B_DIM; b++) {
            unsigned long long a2 = AG[b * 16 + fp];       // warp broadcast
            unsigned long long h2 = HS[b * 16 + fp];       // warp broadcast
            accr[b]  = ffma2(h2, whr, ffma2(a2, wir, accr[b]));
            accz[b]  = ffma2(h2, whz, ffma2(a2, wiz, accz[b]));
            accxn[b] = ffma2(a2, win, accxn[b]);
            acchn[b] = ffma2(h2, whn, acchn[b]);
        }
    }

    // ---- gates + output ----
    const float br  = sBias[lane];
    const float bz  = sBias[32 + lane];
    const float bxn = sBias[64 + lane];
    const float bhn = sBias[96 + lane];
    float* outp = out + ((size_t)c << 5) + lane;
#pragma unroll
    for (int b = 0; b < B_DIM; b++) {
        float r  = sigmoidf_fast(hadd2(accr[b]) + br);
        float z  = sigmoidf_fast(hadd2(accz[b]) + bz);
        float n  = tanhf_fast(hadd2(accxn[b]) + bxn + r * (hadd2(acchn[b]) + bhn));
        float hv = hS[b * 32 + lane];
        outp[(size_t)b * C_DIM * F_DIM] = (1.0f - z) * n + z * hv;  // coalesced STG
    }
}

extern "C" void kernel_launch(void* const* d_in, const int* in_sizes, int n_in,
                              void* d_out, int out_size) {
    (void)in_sizes; (void)n_in; (void)out_size;
    const float* pf  = (const float*)d_in[0];
    const float* hf  = (const float*)d_in[1];
    const float* Wih = (const float*)d_in[2];
    const float* Whh = (const float*)d_in[3];
    const float* bih = (const float*)d_in[4];
    const float* bhh = (const float*)d_in[5];
    const int*   ep  = (const int*)d_in[6];
    const int*   ec  = (const int*)d_in[7];
    float* out = (float*)d_out;

    offsets_kernel<<<(C_DIM + 1 + 255) / 256, 256>>>(ec);
    gru_kernel<<<C_DIM / WARPS, THREADS>>>(pf, hf, Wih, Whh, bih, bhh, ep, out);
}

// round 6
// speedup vs baseline: 2.1502x; 2.1502x over previous
#include <cuda_runtime.h>
#include <cstdint>

// Problem constants (fixed shapes per reference)
#define B_DIM 8
#define P_DIM 65536
#define C_DIM 32768
#define F_DIM 32
#define E_DIM 524288
#define THREADS 256
#define WARPS 8

// Per-channel edge-range offsets (edge_channel is sorted)
__device__ int g_offs[C_DIM + 1];

// ---------- packed f32x2 helpers ----------
__device__ __forceinline__ unsigned long long ffma2(unsigned long long a,
                                                    unsigned long long b,
                                                    unsigned long long c) {
    unsigned long long d;
    asm("fma.rn.f32x2 %0, %1, %2, %3;" : "=l"(d) : "l"(a), "l"(b), "l"(c));
    return d;
}
__device__ __forceinline__ unsigned long long add2(unsigned long long a,
                                                   unsigned long long b) {
    unsigned long long d;
    asm("add.rn.f32x2 %0, %1, %2;" : "=l"(d) : "l"(a), "l"(b));
    return d;
}
__device__ __forceinline__ float hadd2(unsigned long long v) {
    float lo, hi;
    asm("mov.b64 {%0, %1}, %2;" : "=f"(lo), "=f"(hi) : "l"(v));
    return lo + hi;
}
__device__ __forceinline__ float fast_rcp(float x) {
    float r;
    asm("rcp.approx.f32 %0, %1;" : "=f"(r) : "f"(x));
    return r;
}
__device__ __forceinline__ float sigmoidf_fast(float x) {
    return fast_rcp(1.0f + __expf(-x));
}
__device__ __forceinline__ float tanhf_fast(float x) {
    return fmaf(2.0f, sigmoidf_fast(2.0f * x), -1.0f);
}

// ---------- kernel 1: segment offsets via binary search ----------
__global__ void offsets_kernel(const int* __restrict__ ec) {
    int c = blockIdx.x * blockDim.x + threadIdx.x;
    if (c > C_DIM) return;
    int lo = 0, hi = E_DIM;
    while (lo < hi) {
        int mid = (lo + hi) >> 1;
        if (ec[mid] < c) lo = mid + 1; else hi = mid;
    }
    g_offs[c] = lo;  // lower_bound(edge_channel, c); c == C_DIM -> E_DIM
}

// ---------- kernel 2: fused gather + GRU ----------
// One warp per channel. Gather phase: lane = (b = lane>>2, q = lane&3),
// each lane owns features [q*8, q*8+8) of batch b (2 x LDG.128 per edge
// covers all 8 batches x 32 features warp-wide). GEMM phase: lane = output
// feature j.
__global__ __launch_bounds__(THREADS, 2)
void gru_kernel(const float* __restrict__ pf,   // path_features   [B,P,F]
                const float* __restrict__ hf,   // channel_features[B,C,F]
                const float* __restrict__ Wih,  // [3F,F]
                const float* __restrict__ Whh,  // [3F,F]
                const float* __restrict__ bih,  // [3F]
                const float* __restrict__ bhh,  // [3F]
                const int*   __restrict__ ep,   // edge_path [E]
                float*       __restrict__ out)  // [B,C,F]
{
    // Weights as float4 quads: sW[fq][row] = W[row][4fq .. 4fq+3]
    __shared__ float4 sWih[8 * 96];
    __shared__ float4 sWhh[8 * 96];
    __shared__ float  sBias[128];
    // Per-warp staging: x (agg) and h, layout [b][f]
    __shared__ __align__(16) float sA[WARPS][256];
    __shared__ __align__(16) float sH[WARPS][256];

    const int tid = threadIdx.x;

    for (int i = tid; i < 8 * 96; i += THREADS) {
        int fq = i / 96, row = i % 96;
        const float4* wi = (const float4*)(Wih + row * 32 + fq * 4);
        const float4* wh = (const float4*)(Whh + row * 32 + fq * 4);
        sWih[i] = __ldg(wi);
        sWhh[i] = __ldg(wh);
    }
    if (tid < 32) {
        sBias[tid]      = bih[tid]      + bhh[tid];       // r bias (combined)
        sBias[32 + tid] = bih[32 + tid] + bhh[32 + tid];  // z bias (combined)
        sBias[64 + tid] = bih[64 + tid];                  // n input bias
        sBias[96 + tid] = bhh[64 + tid];                  // n hidden bias (inside r*)
    }
    __syncthreads();

    const int w = tid >> 5, lane = tid & 31;
    const int c  = blockIdx.x * WARPS + w;
    const int bb = lane >> 2, q = lane & 3;

    // ---- gather: packed f32x2 accumulators for 8 features of batch bb ----
    unsigned long long a00 = 0ull, a01 = 0ull, a10 = 0ull, a11 = 0ull;
    const float* pfLane = pf + (size_t)bb * (P_DIM * F_DIM) + q * 8;

    const int s0 = g_offs[c], e0 = g_offs[c + 1];
    int i = s0;
    for (; i + 4 <= e0; i += 4) {
        int p0 = __ldg(ep + i);      // uniform loads (1 wavefront each)
        int p1 = __ldg(ep + i + 1);
        int p2 = __ldg(ep + i + 2);
        int p3 = __ldg(ep + i + 3);
        ulonglong2 v00 = *(const ulonglong2*)(pfLane + ((size_t)p0 << 5));
        ulonglong2 v01 = *(const ulonglong2*)(pfLane + ((size_t)p0 << 5) + 4);
        ulonglong2 v10 = *(const ulonglong2*)(pfLane + ((size_t)p1 << 5));
        ulonglong2 v11 = *(const ulonglong2*)(pfLane + ((size_t)p1 << 5) + 4);
        ulonglong2 v20 = *(const ulonglong2*)(pfLane + ((size_t)p2 << 5));
        ulonglong2 v21 = *(const ulonglong2*)(pfLane + ((size_t)p2 << 5) + 4);
        ulonglong2 v30 = *(const ulonglong2*)(pfLane + ((size_t)p3 << 5));
        ulonglong2 v31 = *(const ulonglong2*)(pfLane + ((size_t)p3 << 5) + 4);
        a00 = add2(a00, v00.x); a01 = add2(a01, v00.y);
        a10 = add2(a10, v01.x); a11 = add2(a11, v01.y);
        a00 = add2(a00, v10.x); a01 = add2(a01, v10.y);
        a10 = add2(a10, v11.x); a11 = add2(a11, v11.y);
        a00 = add2(a00, v20.x); a01 = add2(a01, v20.y);
        a10 = add2(a10, v21.x); a11 = add2(a11, v21.y);
        a00 = add2(a00, v30.x); a01 = add2(a01, v30.y);
        a10 = add2(a10, v31.x); a11 = add2(a11, v31.y);
    }
    for (; i < e0; i++) {
        int p = __ldg(ep + i);
        ulonglong2 v0 = *(const ulonglong2*)(pfLane + ((size_t)p << 5));
        ulonglong2 v1 = *(const ulonglong2*)(pfLane + ((size_t)p << 5) + 4);
        a00 = add2(a00, v0.x); a01 = add2(a01, v0.y);
        a10 = add2(a10, v1.x); a11 = add2(a11, v1.y);
    }

    // ---- stage x and h into per-warp shared (vector STS) ----
    {
        ulonglong2 lo; lo.x = a00; lo.y = a01;
        ulonglong2 hi; hi.x = a10; hi.y = a11;
        *(ulonglong2*)&sA[w][bb * 32 + q * 8]     = lo;
        *(ulonglong2*)&sA[w][bb * 32 + q * 8 + 4] = hi;
        const float* hsrc = hf + (size_t)bb * (C_DIM * F_DIM) + ((size_t)c << 5) + q * 8;
        ulonglong2 h0 = *(const ulonglong2*)hsrc;
        ulonglong2 h1 = *(const ulonglong2*)(hsrc + 4);
        *(ulonglong2*)&sH[w][bb * 32 + q * 8]     = h0;
        *(ulonglong2*)&sH[w][bb * 32 + q * 8 + 4] = h1;
    }
    __syncwarp();

    // ---- GEMM: lane j computes gates r/z/n for output feature j, all b ----
    const ulonglong2* WI = (const ulonglong2*)sWih;
    const ulonglong2* WH = (const ulonglong2*)sWhh;

    unsigned long long accr[B_DIM], accz[B_DIM], accxn[B_DIM], acchn[B_DIM];
#pragma unroll
    for (int b = 0; b < B_DIM; b++) { accr[b] = 0ull; accz[b] = 0ull; accxn[b] = 0ull; acchn[b] = 0ull; }

#pragma unroll
    for (int fq = 0; fq < 8; fq++) {
        ulonglong2 wir = WI[fq * 96 + lane];        // conflict-free LDS.128
        ulonglong2 wiz = WI[fq * 96 + 32 + lane];
        ulonglong2 win = WI[fq * 96 + 64 + lane];
        ulonglong2 whr = WH[fq * 96 + lane];
        ulonglong2 whz = WH[fq * 96 + 32 + lane];
        ulonglong2 whn = WH[fq * 96 + 64 + lane];
#pragma unroll
        for (int b = 0; b < B_DIM; b++) {
            ulonglong2 a = *(const ulonglong2*)&sA[w][b * 32 + fq * 4];  // broadcast
            ulonglong2 h = *(const ulonglong2*)&sH[w][b * 32 + fq * 4];  // broadcast
            accr[b]  = ffma2(a.y, wir.y, ffma2(a.x, wir.x, accr[b]));
            accr[b]  = ffma2(h.y, whr.y, ffma2(h.x, whr.x, accr[b]));
            accz[b]  = ffma2(a.y, wiz.y, ffma2(a.x, wiz.x, accz[b]));
            accz[b]  = ffma2(h.y, whz.y, ffma2(h.x, whz.x, accz[b]));
            accxn[b] = ffma2(a.y, win.y, ffma2(a.x, win.x, accxn[b]));
            acchn[b] = ffma2(h.y, whn.y, ffma2(h.x, whn.x, acchn[b]));
        }
    }

    // ---- gates + output (lane = feature) ----
    const float br  = sBias[lane];
    const float bz  = sBias[32 + lane];
    const float bxn = sBias[64 + lane];
    const float bhn = sBias[96 + lane];
    float* outp = out + ((size_t)c << 5) + lane;
#pragma unroll
    for (int b = 0; b < B_DIM; b++) {
        float r  = sigmoidf_fast(hadd2(accr[b]) + br);
        float z  = sigmoidf_fast(hadd2(accz[b]) + bz);
        float n  = tanhf_fast(hadd2(accxn[b]) + bxn + r * (hadd2(acchn[b]) + bhn));
        float hv = sH[w][b * 32 + lane];
        outp[(size_t)b * (C_DIM * F_DIM)] = (1.0f - z) * n + z * hv;  // coalesced STG
    }
}

extern "C" void kernel_launch(void* const* d_in, const int* in_sizes, int n_in,
                              void* d_out, int out_size) {
    (void)in_sizes; (void)n_in; (void)out_size;
    const float* pf  = (const float*)d_in[0];
    const float* hf  = (const float*)d_in[1];
    const float* Wih = (const float*)d_in[2];
    const float* Whh = (const float*)d_in[3];
    const float* bih = (const float*)d_in[4];
    const float* bhh = (const float*)d_in[5];
    const int*   ep  = (const int*)d_in[6];
    const int*   ec  = (const int*)d_in[7];
    float* out = (float*)d_out;

    offsets_kernel<<<(C_DIM + 1 + 255) / 256, 256>>>(ec);
    gru_kernel<<<C_DIM / WARPS, THREADS>>>(pf, hf, Wih, Whh, bih, bhh, ep, out);
}

// round 7
// speedup vs baseline: 2.3431x; 1.0897x over previous
#include <cuda_runtime.h>
#include <cstdint>

// Problem constants (fixed shapes per reference)
#define B_DIM 8
#define P_DIM 65536
#define C_DIM 32768
#define F_DIM 32
#define E_DIM 524288
#define THREADS 256
#define WARPS 8

// Per-channel edge-range offsets (edge_channel is sorted)
__device__ int g_offs[C_DIM + 1];

// ---------- packed f32x2 helpers ----------
__device__ __forceinline__ unsigned long long ffma2(unsigned long long a,
                                                    unsigned long long b,
                                                    unsigned long long c) {
    unsigned long long d;
    asm("fma.rn.f32x2 %0, %1, %2, %3;" : "=l"(d) : "l"(a), "l"(b), "l"(c));
    return d;
}
__device__ __forceinline__ unsigned long long add2(unsigned long long a,
                                                   unsigned long long b) {
    unsigned long long d;
    asm("add.rn.f32x2 %0, %1, %2;" : "=l"(d) : "l"(a), "l"(b));
    return d;
}
__device__ __forceinline__ float hadd2(unsigned long long v) {
    float lo, hi;
    asm("mov.b64 {%0, %1}, %2;" : "=f"(lo), "=f"(hi) : "l"(v));
    return lo + hi;
}
__device__ __forceinline__ float fast_rcp(float x) {
    float r;
    asm("rcp.approx.f32 %0, %1;" : "=f"(r) : "f"(x));
    return r;
}
__device__ __forceinline__ float sigmoidf_fast(float x) {
    return fast_rcp(1.0f + __expf(-x));
}
__device__ __forceinline__ float tanhf_fast(float x) {
    return fmaf(2.0f, sigmoidf_fast(2.0f * x), -1.0f);
}

// ---------- kernel 1: segment offsets via binary search ----------
__global__ void offsets_kernel(const int* __restrict__ ec) {
    int c = blockIdx.x * blockDim.x + threadIdx.x;
    if (c > C_DIM) return;
    int lo = 0, hi = E_DIM;
    while (lo < hi) {
        int mid = (lo + hi) >> 1;
        if (ec[mid] < c) lo = mid + 1; else hi = mid;
    }
    g_offs[c] = lo;  // lower_bound(edge_channel, c); c == C_DIM -> E_DIM
}

// ---------- kernel 2: fused gather + GRU ----------
// One warp per channel. Gather phase: lane = (bb = lane>>3, q8 = lane&7);
// lane loads the contiguous float4 at features [q8*4, q8*4+4) of batch bb
// (instr A) and batch bb+4 (instr B). Each 128B path row is covered by
// exactly one LDG.128 instruction (8 lanes x 16B contiguous) -> no wasted
// wavefronts, each L2 sector requested once. GEMM phase: lane = output
// feature j.
__global__ __launch_bounds__(THREADS, 2)
void gru_kernel(const float* __restrict__ pf,   // path_features   [B,P,F]
                const float* __restrict__ hf,   // channel_features[B,C,F]
                const float* __restrict__ Wih,  // [3F,F]
                const float* __restrict__ Whh,  // [3F,F]
                const float* __restrict__ bih,  // [3F]
                const float* __restrict__ bhh,  // [3F]
                const int*   __restrict__ ep,   // edge_path [E]
                float*       __restrict__ out)  // [B,C,F]
{
    // Weights as float4 quads: sW[fq][row] = W[row][4fq .. 4fq+3]
    __shared__ float4 sWih[8 * 96];
    __shared__ float4 sWhh[8 * 96];
    __shared__ float  sBias[128];
    // Per-warp staging: x (agg) and h, layout [b][f]
    __shared__ __align__(16) float sA[WARPS][256];
    __shared__ __align__(16) float sH[WARPS][256];

    const int tid = threadIdx.x;

    for (int i = tid; i < 8 * 96; i += THREADS) {
        int fq = i / 96, row = i % 96;
        sWih[i] = __ldg((const float4*)(Wih + row * 32 + fq * 4));
        sWhh[i] = __ldg((const float4*)(Whh + row * 32 + fq * 4));
    }
    if (tid < 32) {
        sBias[tid]      = bih[tid]      + bhh[tid];       // r bias (combined)
        sBias[32 + tid] = bih[32 + tid] + bhh[32 + tid];  // z bias (combined)
        sBias[64 + tid] = bih[64 + tid];                  // n input bias
        sBias[96 + tid] = bhh[64 + tid];                  // n hidden bias (inside r*)
    }
    __syncthreads();

    const int w = tid >> 5, lane = tid & 31;
    const int c   = blockIdx.x * WARPS + w;
    const int bb  = lane >> 3;       // batch 0..3 (and bb+4 for second half)
    const int q8  = lane & 7;        // feature quad 0..7

    // ---- gather: two float4 accumulators (batch bb and batch bb+4) ----
    unsigned long long aA0 = 0ull, aA1 = 0ull;   // batch bb,   feats q8*4..+4
    unsigned long long aB0 = 0ull, aB1 = 0ull;   // batch bb+4, feats q8*4..+4
    const float* pfA = pf + (size_t)bb * (P_DIM * F_DIM) + q8 * 4;
    const float* pfB = pfA + (size_t)4 * (P_DIM * F_DIM);

    const int s0 = g_offs[c], e0 = g_offs[c + 1];
    int i = s0;
    for (; i + 8 <= e0; i += 8) {
        int p0 = __ldg(ep + i + 0);
        int p1 = __ldg(ep + i + 1);
        int p2 = __ldg(ep + i + 2);
        int p3 = __ldg(ep + i + 3);
        int p4 = __ldg(ep + i + 4);
        int p5 = __ldg(ep + i + 5);
        int p6 = __ldg(ep + i + 6);
        int p7 = __ldg(ep + i + 7);
        ulonglong2 vA0 = *(const ulonglong2*)(pfA + ((size_t)p0 << 5));
        ulonglong2 vB0 = *(const ulonglong2*)(pfB + ((size_t)p0 << 5));
        ulonglong2 vA1 = *(const ulonglong2*)(pfA + ((size_t)p1 << 5));
        ulonglong2 vB1 = *(const ulonglong2*)(pfB + ((size_t)p1 << 5));
        ulonglong2 vA2 = *(const ulonglong2*)(pfA + ((size_t)p2 << 5));
        ulonglong2 vB2 = *(const ulonglong2*)(pfB + ((size_t)p2 << 5));
        ulonglong2 vA3 = *(const ulonglong2*)(pfA + ((size_t)p3 << 5));
        ulonglong2 vB3 = *(const ulonglong2*)(pfB + ((size_t)p3 << 5));
        ulonglong2 vA4 = *(const ulonglong2*)(pfA + ((size_t)p4 << 5));
        ulonglong2 vB4 = *(const ulonglong2*)(pfB + ((size_t)p4 << 5));
        ulonglong2 vA5 = *(const ulonglong2*)(pfA + ((size_t)p5 << 5));
        ulonglong2 vB5 = *(const ulonglong2*)(pfB + ((size_t)p5 << 5));
        ulonglong2 vA6 = *(const ulonglong2*)(pfA + ((size_t)p6 << 5));
        ulonglong2 vB6 = *(const ulonglong2*)(pfB + ((size_t)p6 << 5));
        ulonglong2 vA7 = *(const ulonglong2*)(pfA + ((size_t)p7 << 5));
        ulonglong2 vB7 = *(const ulonglong2*)(pfB + ((size_t)p7 << 5));
        aA0 = add2(aA0, vA0.x); aA1 = add2(aA1, vA0.y);
        aB0 = add2(aB0, vB0.x); aB1 = add2(aB1, vB0.y);
        aA0 = add2(aA0, vA1.x); aA1 = add2(aA1, vA1.y);
        aB0 = add2(aB0, vB1.x); aB1 = add2(aB1, vB1.y);
        aA0 = add2(aA0, vA2.x); aA1 = add2(aA1, vA2.y);
        aB0 = add2(aB0, vB2.x); aB1 = add2(aB1, vB2.y);
        aA0 = add2(aA0, vA3.x); aA1 = add2(aA1, vA3.y);
        aB0 = add2(aB0, vB3.x); aB1 = add2(aB1, vB3.y);
        aA0 = add2(aA0, vA4.x); aA1 = add2(aA1, vA4.y);
        aB0 = add2(aB0, vB4.x); aB1 = add2(aB1, vB4.y);
        aA0 = add2(aA0, vA5.x); aA1 = add2(aA1, vA5.y);
        aB0 = add2(aB0, vB5.x); aB1 = add2(aB1, vB5.y);
        aA0 = add2(aA0, vA6.x); aA1 = add2(aA1, vA6.y);
        aB0 = add2(aB0, vB6.x); aB1 = add2(aB1, vB6.y);
        aA0 = add2(aA0, vA7.x); aA1 = add2(aA1, vA7.y);
        aB0 = add2(aB0, vB7.x); aB1 = add2(aB1, vB7.y);
    }
    for (; i < e0; i++) {
        int p = __ldg(ep + i);
        ulonglong2 vA = *(const ulonglong2*)(pfA + ((size_t)p << 5));
        ulonglong2 vB = *(const ulonglong2*)(pfB + ((size_t)p << 5));
        aA0 = add2(aA0, vA.x); aA1 = add2(aA1, vA.y);
        aB0 = add2(aB0, vB.x); aB1 = add2(aB1, vB.y);
    }

    // ---- stage x and h into per-warp shared (vector STS, conflict-free) ----
    {
        ulonglong2 accA; accA.x = aA0; accA.y = aA1;
        ulonglong2 accB; accB.x = aB0; accB.y = aB1;
        *(ulonglong2*)&sA[w][bb * 32 + q8 * 4]       = accA;
        *(ulonglong2*)&sA[w][(bb + 4) * 32 + q8 * 4] = accB;
        const float* hA = hf + (size_t)bb * (C_DIM * F_DIM) + ((size_t)c << 5) + q8 * 4;
        const float* hB = hA + (size_t)4 * (C_DIM * F_DIM);
        ulonglong2 hvA = *(const ulonglong2*)hA;   // coalesced 128B per batch row
        ulonglong2 hvB = *(const ulonglong2*)hB;
        *(ulonglong2*)&sH[w][bb * 32 + q8 * 4]       = hvA;
        *(ulonglong2*)&sH[w][(bb + 4) * 32 + q8 * 4] = hvB;
    }
    __syncwarp();

    // ---- GEMM: lane j computes gates r/z/n for output feature j, all b ----
    const ulonglong2* WI = (const ulonglong2*)sWih;
    const ulonglong2* WH = (const ulonglong2*)sWhh;

    unsigned long long accr[B_DIM], accz[B_DIM], accxn[B_DIM], acchn[B_DIM];
#pragma unroll
    for (int b = 0; b < B_DIM; b++) { accr[b] = 0ull; accz[b] = 0ull; accxn[b] = 0ull; acchn[b] = 0ull; }

#pragma unroll
    for (int fq = 0; fq < 8; fq++) {
        ulonglong2 wir = WI[fq * 96 + lane];        // conflict-free LDS.128
        ulonglong2 wiz = WI[fq * 96 + 32 + lane];
        ulonglong2 win = WI[fq * 96 + 64 + lane];
        ulonglong2 whr = WH[fq * 96 + lane];
        ulonglong2 whz = WH[fq * 96 + 32 + lane];
        ulonglong2 whn = WH[fq * 96 + 64 + lane];
#pragma unroll
        for (int b = 0; b < B_DIM; b++) {
            ulonglong2 a = *(const ulonglong2*)&sA[w][b * 32 + fq * 4];  // broadcast
            ulonglong2 h = *(const ulonglong2*)&sH[w][b * 32 + fq * 4];  // broadcast
            accr[b]  = ffma2(a.y, wir.y, ffma2(a.x, wir.x, accr[b]));
            accr[b]  = ffma2(h.y, whr.y, ffma2(h.x, whr.x, accr[b]));
            accz[b]  = ffma2(a.y, wiz.y, ffma2(a.x, wiz.x, accz[b]));
            accz[b]  = ffma2(h.y, whz.y, ffma2(h.x, whz.x, accz[b]));
            accxn[b] = ffma2(a.y, win.y, ffma2(a.x, win.x, accxn[b]));
            acchn[b] = ffma2(h.y, whn.y, ffma2(h.x, whn.x, acchn[b]));
        }
    }

    // ---- gates + output (lane = feature) ----
    const float br  = sBias[lane];
    const float bz  = sBias[32 + lane];
    const float bxn = sBias[64 + lane];
    const float bhn = sBias[96 + lane];
    float* outp = out + ((size_t)c << 5) + lane;
#pragma unroll
    for (int b = 0; b < B_DIM; b++) {
        float r  = sigmoidf_fast(hadd2(accr[b]) + br);
        float z  = sigmoidf_fast(hadd2(accz[b]) + bz);
        float n  = tanhf_fast(hadd2(accxn[b]) + bxn + r * (hadd2(acchn[b]) + bhn));
        float hv = sH[w][b * 32 + lane];
        outp[(size_t)b * (C_DIM * F_DIM)] = (1.0f - z) * n + z * hv;  // coalesced STG
    }
}

extern "C" void kernel_launch(void* const* d_in, const int* in_sizes, int n_in,
                              void* d_out, int out_size) {
    (void)in_sizes; (void)n_in; (void)out_size;
    const float* pf  = (const float*)d_in[0];
    const float* hf  = (const float*)d_in[1];
    const float* Wih = (const float*)d_in[2];
    const float* Whh = (const float*)d_in[3];
    const float* bih = (const float*)d_in[4];
    const float* bhh = (const float*)d_in[5];
    const int*   ep  = (const int*)d_in[6];
    const int*   ec  = (const int*)d_in[7];
    float* out = (float*)d_out;

    offsets_kernel<<<(C_DIM + 1 + 255) / 256, 256>>>(ec);
    gru_kernel<<<C_DIM / WARPS, THREADS>>>(pf, hf, Wih, Whh, bih, bhh, ep, out);
}